// round 1
// baseline (speedup 1.0000x reference)
#include <cuda_runtime.h>
#include <math.h>

#define NHEADS 16
#define SEQ    2048
#define DMODEL 1024
#define BATCH  2
#define DK     64
#define QKVC   (3 * DMODEL)   // 3072
#define ROWS   (BATCH * SEQ)  // 4096

// ---------------- scratch (static device globals; no allocation) ----------------
__device__ float g_qkv[(size_t)ROWS * QKVC];     // (B*N, 3D) qkv projection
__device__ float g_ctx[(size_t)ROWS * DMODEL];   // (B, N, H*dk) context
__device__ float g_colsum[BATCH * SEQ];          // attn column sums

// ---------------- zero colsum ----------------
__global__ void zero_colsum_kernel() {
    int i = blockIdx.x * blockDim.x + threadIdx.x;
    if (i < BATCH * SEQ) g_colsum[i] = 0.0f;
}

// ---------------- generic GEMM: C = A(MxK) @ B(KxN) + bias(N) ----------------
// 128x128 tile, BK=8, 256 threads, 8x8 per thread.
__global__ __launch_bounds__(256) void gemm_bias_kernel(
    const float* __restrict__ A, const float* __restrict__ B,
    const float* __restrict__ bias, float* __restrict__ C,
    int M, int N, int K)
{
    __shared__ float As[8][128];
    __shared__ float Bs[8][128];

    const int tid = threadIdx.x;
    const int tx = tid & 15;        // 0..15 -> col group
    const int ty = tid >> 4;        // 0..15 -> row group
    const int bx = blockIdx.x;      // N tile
    const int by = blockIdx.y;      // M tile

    const int ar = tid >> 1;            // 0..127
    const int ac = (tid & 1) * 4;       // 0 or 4
    const int br = tid >> 5;            // 0..7
    const int bc = (tid & 31) * 4;      // 0..124

    const float* Aptr = A + (size_t)(by * 128 + ar) * K + ac;
    const float* Bptr = B + (size_t)br * N + bx * 128 + bc;

    float acc[8][8];
#pragma unroll
    for (int i = 0; i < 8; i++)
#pragma unroll
        for (int j = 0; j < 8; j++) acc[i][j] = 0.0f;

    for (int k0 = 0; k0 < K; k0 += 8) {
        float4 a = *(const float4*)(Aptr + k0);
        As[ac + 0][ar] = a.x;
        As[ac + 1][ar] = a.y;
        As[ac + 2][ar] = a.z;
        As[ac + 3][ar] = a.w;
        *(float4*)&Bs[br][bc] = *(const float4*)(Bptr + (size_t)k0 * N);
        __syncthreads();

#pragma unroll
        for (int kk = 0; kk < 8; kk++) {
            float4 a0 = *(const float4*)&As[kk][ty * 8];
            float4 a1 = *(const float4*)&As[kk][ty * 8 + 4];
            float4 b0 = *(const float4*)&Bs[kk][tx * 8];
            float4 b1 = *(const float4*)&Bs[kk][tx * 8 + 4];
            float af[8] = {a0.x, a0.y, a0.z, a0.w, a1.x, a1.y, a1.z, a1.w};
            float bf[8] = {b0.x, b0.y, b0.z, b0.w, b1.x, b1.y, b1.z, b1.w};
#pragma unroll
            for (int i = 0; i < 8; i++)
#pragma unroll
                for (int j = 0; j < 8; j++) acc[i][j] += af[i] * bf[j];
        }
        __syncthreads();
    }

    // epilogue with bias
#pragma unroll
    for (int i = 0; i < 8; i++) {
        int row = by * 128 + ty * 8 + i;
        float* Cp = C + (size_t)row * N + bx * 128 + tx * 8;
        const float* bp = bias + bx * 128 + tx * 8;
        float4 c0 = make_float4(acc[i][0] + bp[0], acc[i][1] + bp[1],
                                acc[i][2] + bp[2], acc[i][3] + bp[3]);
        float4 c1 = make_float4(acc[i][4] + bp[4], acc[i][5] + bp[5],
                                acc[i][6] + bp[6], acc[i][7] + bp[7]);
        *(float4*)Cp = c0;
        *(float4*)(Cp + 4) = c1;
    }
}

// ---------------- flash attention + colsum ----------------
// Block: 256 threads, handles 64 query rows of one (b, h).
// grid = (SEQ/64, BATCH*NHEADS)
#define KP_STRIDE 68   // padded row stride for Kt / Ps buffer (float4-aligned, low conflict)
#define FLASH_SMEM_FLOATS (4096 /*Qt*/ + 64 * KP_STRIDE /*Kt|Ps*/ + 4096 /*Vs*/ + 64 /*cs*/)

__global__ __launch_bounds__(256) void flash_kernel(
    const float* __restrict__ qkv, float* __restrict__ ctx,
    float* __restrict__ colsum)
{
    extern __shared__ float sm[];
    float* Qt  = sm;                      // [64][64]  Qt[d][r], scaled
    float* KtP = sm + 4096;               // [64][68]  Kt[d][c]  then  Ps[m][r]
    float* Vs  = KtP + 64 * KP_STRIDE;    // [64][64]  Vs[m][d]
    float* cs  = Vs + 4096;               // [64] per-tile column sums

    const int tid = threadIdx.x;
    const int tx = tid & 15;   // col group
    const int ty = tid >> 4;   // row group
    const int qtile = blockIdx.x;
    const int b = blockIdx.y >> 4;
    const int h = blockIdx.y & 15;

    const float* base = qkv + (size_t)b * SEQ * QKVC + h * (3 * DK);

    // ---- load Q tile (scaled by 1/sqrt(dk)=0.125), transposed ----
#pragma unroll
    for (int i = 0; i < 4; i++) {
        int f = tid + i * 256;
        int r = f >> 4;
        int dg = (f & 15) << 2;
        float4 v = *(const float4*)(base + (size_t)(qtile * 64 + r) * QKVC + dg);
        Qt[(dg + 0) * 64 + r] = v.x * 0.125f;
        Qt[(dg + 1) * 64 + r] = v.y * 0.125f;
        Qt[(dg + 2) * 64 + r] = v.z * 0.125f;
        Qt[(dg + 3) * 64 + r] = v.w * 0.125f;
    }
    if (tid < 64) cs[tid] = 0.0f;

    float m_i[4], l_i[4], O[4][4];
#pragma unroll
    for (int i = 0; i < 4; i++) {
        m_i[i] = -1e30f;
        l_i[i] = 0.0f;
#pragma unroll
        for (int j = 0; j < 4; j++) O[i][j] = 0.0f;
    }
    __syncthreads();

    // ---- main flash loop over key tiles ----
    for (int t = 0; t < SEQ / 64; t++) {
        // load K (transposed) and V tiles
#pragma unroll
        for (int i = 0; i < 4; i++) {
            int f = tid + i * 256;
            int r = f >> 4;
            int dg = (f & 15) << 2;
            const float* rowp = base + (size_t)(t * 64 + r) * QKVC;
            float4 kv = *(const float4*)(rowp + DK + dg);
            KtP[(dg + 0) * KP_STRIDE + r] = kv.x;
            KtP[(dg + 1) * KP_STRIDE + r] = kv.y;
            KtP[(dg + 2) * KP_STRIDE + r] = kv.z;
            KtP[(dg + 3) * KP_STRIDE + r] = kv.w;
            *(float4*)&Vs[r * 64 + dg] = *(const float4*)(rowp + 2 * DK + dg);
        }
        __syncthreads();

        // S = Q K^T (scaled)
        float s[4][4];
#pragma unroll
        for (int i = 0; i < 4; i++)
#pragma unroll
            for (int j = 0; j < 4; j++) s[i][j] = 0.0f;

#pragma unroll 8
        for (int d = 0; d < 64; d++) {
            float4 qv = *(const float4*)&Qt[d * 64 + ty * 4];
            float4 kv = *(const float4*)&KtP[d * KP_STRIDE + tx * 4];
            float q[4] = {qv.x, qv.y, qv.z, qv.w};
            float k[4] = {kv.x, kv.y, kv.z, kv.w};
#pragma unroll
            for (int i = 0; i < 4; i++)
#pragma unroll
                for (int j = 0; j < 4; j++) s[i][j] += q[i] * k[j];
        }

        // online softmax update
#pragma unroll
        for (int i = 0; i < 4; i++) {
            float mx = fmaxf(fmaxf(s[i][0], s[i][1]), fmaxf(s[i][2], s[i][3]));
#pragma unroll
            for (int off = 8; off >= 1; off >>= 1)
                mx = fmaxf(mx, __shfl_xor_sync(0xffffffffu, mx, off, 16));
            float mnew = fmaxf(m_i[i], mx);
            float corr = __expf(m_i[i] - mnew);
            l_i[i] *= corr;
#pragma unroll
            for (int j = 0; j < 4; j++) O[i][j] *= corr;
            float rsum = 0.0f;
#pragma unroll
            for (int j = 0; j < 4; j++) {
                s[i][j] = __expf(s[i][j] - mnew);  // s becomes P
                rsum += s[i][j];
            }
#pragma unroll
            for (int off = 8; off >= 1; off >>= 1)
                rsum += __shfl_xor_sync(0xffffffffu, rsum, off, 16);
            l_i[i] += rsum;
            m_i[i] = mnew;
        }

        __syncthreads();  // everyone done reading Kt before overwriting with Ps

        // store P transposed: Ps[m][r]
#pragma unroll
        for (int i = 0; i < 4; i++)
#pragma unroll
            for (int j = 0; j < 4; j++)
                KtP[(tx * 4 + j) * KP_STRIDE + ty * 4 + i] = s[i][j];
        __syncthreads();

        // O += P @ V
#pragma unroll 8
        for (int m = 0; m < 64; m++) {
            float4 pv = *(const float4*)&KtP[m * KP_STRIDE + ty * 4];
            float4 vv = *(const float4*)&Vs[m * 64 + tx * 4];
            float p[4] = {pv.x, pv.y, pv.z, pv.w};
            float v[4] = {vv.x, vv.y, vv.z, vv.w};
#pragma unroll
            for (int i = 0; i < 4; i++)
#pragma unroll
                for (int j = 0; j < 4; j++) O[i][j] += p[i] * v[j];
        }
        __syncthreads();  // before next tile overwrites Kt / Vs
    }

    // ---- epilogue: normalized context in (B, N, H*dk) layout ----
#pragma unroll
    for (int i = 0; i < 4; i++) {
        float inv = 1.0f / l_i[i];
        int r = qtile * 64 + ty * 4 + i;
        float4 o = make_float4(O[i][0] * inv, O[i][1] * inv,
                               O[i][2] * inv, O[i][3] * inv);
        *(float4*)&ctx[(size_t)b * SEQ * DMODEL + (size_t)r * DMODEL +
                       h * DK + tx * 4] = o;
    }

    // ---- second pass: attn column sums: sum_n exp(s) * exp(-m_n)/l_n ----
    float w[4];
#pragma unroll
    for (int i = 0; i < 4; i++) w[i] = __expf(-m_i[i]) / l_i[i];

    for (int t = 0; t < SEQ / 64; t++) {
        __syncthreads();  // prev reads of KtP / cs housekeeping done
#pragma unroll
        for (int i = 0; i < 4; i++) {
            int f = tid + i * 256;
            int r = f >> 4;
            int dg = (f & 15) << 2;
            const float* rowp = base + (size_t)(t * 64 + r) * QKVC;
            float4 kv = *(const float4*)(rowp + DK + dg);
            KtP[(dg + 0) * KP_STRIDE + r] = kv.x;
            KtP[(dg + 1) * KP_STRIDE + r] = kv.y;
            KtP[(dg + 2) * KP_STRIDE + r] = kv.z;
            KtP[(dg + 3) * KP_STRIDE + r] = kv.w;
        }
        __syncthreads();

        float s[4][4];
#pragma unroll
        for (int i = 0; i < 4; i++)
#pragma unroll
            for (int j = 0; j < 4; j++) s[i][j] = 0.0f;
#pragma unroll 8
        for (int d = 0; d < 64; d++) {
            float4 qv = *(const float4*)&Qt[d * 64 + ty * 4];
            float4 kv = *(const float4*)&KtP[d * KP_STRIDE + tx * 4];
            float q[4] = {qv.x, qv.y, qv.z, qv.w};
            float k[4] = {kv.x, kv.y, kv.z, kv.w};
#pragma unroll
            for (int i = 0; i < 4; i++)
#pragma unroll
                for (int j = 0; j < 4; j++) s[i][j] += q[i] * k[j];
        }

        float c[4] = {0.0f, 0.0f, 0.0f, 0.0f};
#pragma unroll
        for (int i = 0; i < 4; i++)
#pragma unroll
            for (int j = 0; j < 4; j++) c[j] += __expf(s[i][j]) * w[i];
#pragma unroll
        for (int j = 0; j < 4; j++) atomicAdd(&cs[tx * 4 + j], c[j]);
        __syncthreads();

        if (tid < 64) {
            atomicAdd(&colsum[b * SEQ + t * 64 + tid], cs[tid]);
            cs[tid] = 0.0f;
        }
    }
}

// ---------------- finalize attn_mean ----------------
__global__ void finalize_mean_kernel(float* __restrict__ out_mean) {
    int i = blockIdx.x * blockDim.x + threadIdx.x;
    if (i < BATCH * SEQ)
        out_mean[i] = g_colsum[i] * (1.0f / (float)(NHEADS * SEQ));
}

// ---------------- launch ----------------
extern "C" void kernel_launch(void* const* d_in, const int* in_sizes, int n_in,
                              void* d_out, int out_size) {
    const float* x     = (const float*)d_in[0];
    const float* w_qkv = (const float*)d_in[1];
    const float* b_qkv = (const float*)d_in[2];
    const float* w_out = (const float*)d_in[3];
    const float* b_out = (const float*)d_in[4];
    float* out = (float*)d_out;

    float *qkv_p, *ctx_p, *colsum_p;
    cudaGetSymbolAddress((void**)&qkv_p, g_qkv);
    cudaGetSymbolAddress((void**)&ctx_p, g_ctx);
    cudaGetSymbolAddress((void**)&colsum_p, g_colsum);

    const int flash_smem = FLASH_SMEM_FLOATS * (int)sizeof(float);  // ~50.4 KB
    cudaFuncSetAttribute(flash_kernel,
                         cudaFuncAttributeMaxDynamicSharedMemorySize, flash_smem);

    zero_colsum_kernel<<<(BATCH * SEQ + 255) / 256, 256>>>();

    // QKV projection: (4096 x 1024) @ (1024 x 3072) + bias
    gemm_bias_kernel<<<dim3(QKVC / 128, ROWS / 128), 256>>>(
        x, w_qkv, b_qkv, qkv_p, ROWS, QKVC, DMODEL);

    // flash attention + colsum
    flash_kernel<<<dim3(SEQ / 64, BATCH * NHEADS), 256, flash_smem>>>(
        qkv_p, ctx_p, colsum_p);

    // output projection: (4096 x 1024) @ (1024 x 1024) + bias -> d_out head
    gemm_bias_kernel<<<dim3(DMODEL / 128, ROWS / 128), 256>>>(
        ctx_p, w_out, b_out, out, ROWS, DMODEL, DMODEL);

    // attn_mean tail
    finalize_mean_kernel<<<(BATCH * SEQ + 255) / 256, 256>>>(
        out + (size_t)ROWS * DMODEL);
}

// round 2
// speedup vs baseline: 2.3637x; 2.3637x over previous
#include <cuda_runtime.h>
#include <cuda_bf16.h>
#include <math.h>

#define NHEADS 16
#define SEQ    2048
#define DMODEL 1024
#define BATCH  2
#define DK     64
#define QKVC   (3 * DMODEL)   // 3072
#define ROWS   (BATCH * SEQ)  // 4096
#define NKT    (SEQ / 64)     // 32 key tiles
#define QB     128            // flash query rows per block
#define KT     64             // flash key tile

// ---------------- scratch ----------------
__device__ float g_qkv[(size_t)ROWS * QKVC];
__device__ float g_ctx[(size_t)ROWS * DMODEL];
__device__ float g_colsum[BATCH * SEQ];
__device__ __nv_bfloat16 g_p[(size_t)BATCH * NHEADS * NKT * SEQ * KT]; // 256MB P cache
__device__ float g_mt[(size_t)BATCH * NHEADS * NKT * SEQ];             // running max per (row,tile)
__device__ float g_mf[BATCH * NHEADS * SEQ];                           // final max
__device__ float g_il[BATCH * NHEADS * SEQ];                           // 1/l final

// ---------------- packed f32x2 helpers ----------------
union F2U { float2 f2; unsigned long long u; float f[2]; };

__device__ __forceinline__ void fma2(F2U& d, const F2U& a, const F2U& b) {
    asm("fma.rn.f32x2 %0, %1, %2, %0;" : "+l"(d.u) : "l"(a.u), "l"(b.u));
}
__device__ __forceinline__ void mul2(F2U& d, const F2U& a) {
    asm("mul.rn.f32x2 %0, %0, %1;" : "+l"(d.u) : "l"(a.u));
}

// ---------------- misc kernels ----------------
__global__ void zero_colsum_kernel() {
    int i = blockIdx.x * blockDim.x + threadIdx.x;
    if (i < BATCH * SEQ) g_colsum[i] = 0.0f;
}
__global__ void finalize_mean_kernel(float* __restrict__ out_mean) {
    int i = blockIdx.x * blockDim.x + threadIdx.x;
    if (i < BATCH * SEQ)
        out_mean[i] = g_colsum[i] * (1.0f / (float)(NHEADS * SEQ));
}

// ---------------- dense GEMM: C = A(MxK)@B(KxN) + bias, f32x2, 128x128x16, dbuf ----------------
#define ASW_S 130
#define BSW_S 160
#define BSW(c) ((c) + ((c) >> 2))

__global__ __launch_bounds__(256, 2) void gemm_f32x2(
    const float* __restrict__ A, const float* __restrict__ B,
    const float* __restrict__ bias, float* __restrict__ C,
    int N, int K)
{
    __shared__ float As[2][16 * ASW_S];
    __shared__ float Bs[2][16 * BSW_S];

    const int tid = threadIdx.x;
    const int tx = tid & 15, ty = tid >> 4;
    const int bx = blockIdx.x, by = blockIdx.y;

    const int ar = tid >> 1, ac = (tid & 1) * 8;
    const int br0 = tid >> 5, bc0 = (tid & 31) * 4;
    const int br1 = br0 + 8;

    const float* Ap = A + (size_t)(by * 128 + ar) * K + ac;
    const float* Bp = B + (size_t)bx * 128;

    // prologue: load tile 0
    {
        float4 a0 = *(const float4*)(Ap);
        float4 a1 = *(const float4*)(Ap + 4);
        float4 b0 = *(const float4*)(Bp + (size_t)br0 * N + bc0);
        float4 b1 = *(const float4*)(Bp + (size_t)br1 * N + bc0);
        float av[8] = {a0.x, a0.y, a0.z, a0.w, a1.x, a1.y, a1.z, a1.w};
#pragma unroll
        for (int u = 0; u < 8; u++) As[0][(ac + u) * ASW_S + ar] = av[u];
        float bv0[4] = {b0.x, b0.y, b0.z, b0.w};
        float bv1[4] = {b1.x, b1.y, b1.z, b1.w};
#pragma unroll
        for (int u = 0; u < 4; u++) {
            Bs[0][br0 * BSW_S + BSW(bc0 + u)] = bv0[u];
            Bs[0][br1 * BSW_S + BSW(bc0 + u)] = bv1[u];
        }
    }
    __syncthreads();

    F2U acc[4][8];
#pragma unroll
    for (int rp = 0; rp < 4; rp++)
#pragma unroll
        for (int j = 0; j < 8; j++) { acc[rp][j].f[0] = 0.0f; acc[rp][j].f[1] = 0.0f; }

    const int nt = K / 16;
    for (int t = 0; t < nt; ++t) {
        const int cur = t & 1;
        float4 a0n, a1n, b0n, b1n;
        if (t + 1 < nt) {
            int k0 = (t + 1) * 16;
            a0n = *(const float4*)(Ap + k0);
            a1n = *(const float4*)(Ap + k0 + 4);
            b0n = *(const float4*)(Bp + (size_t)(k0 + br0) * N + bc0);
            b1n = *(const float4*)(Bp + (size_t)(k0 + br1) * N + bc0);
        }
#pragma unroll
        for (int kk = 0; kk < 16; ++kk) {
            F2U a[4];
#pragma unroll
            for (int rp = 0; rp < 4; rp++)
                a[rp].f2 = *(const float2*)&As[cur][kk * ASW_S + ty * 8 + 2 * rp];
#pragma unroll
            for (int j = 0; j < 8; j++) {
                float bv = Bs[cur][kk * BSW_S + 10 * tx + j + (j >> 2)];
                F2U bd; bd.f[0] = bv; bd.f[1] = bv;
#pragma unroll
                for (int rp = 0; rp < 4; rp++) fma2(acc[rp][j], a[rp], bd);
            }
        }
        if (t + 1 < nt) {
            const int nxt = cur ^ 1;
            float av[8] = {a0n.x, a0n.y, a0n.z, a0n.w, a1n.x, a1n.y, a1n.z, a1n.w};
#pragma unroll
            for (int u = 0; u < 8; u++) As[nxt][(ac + u) * ASW_S + ar] = av[u];
            float bv0[4] = {b0n.x, b0n.y, b0n.z, b0n.w};
            float bv1[4] = {b1n.x, b1n.y, b1n.z, b1n.w};
#pragma unroll
            for (int u = 0; u < 4; u++) {
                Bs[nxt][br0 * BSW_S + BSW(bc0 + u)] = bv0[u];
                Bs[nxt][br1 * BSW_S + BSW(bc0 + u)] = bv1[u];
            }
        }
        __syncthreads();
    }

    // epilogue + bias
    float bb[8];
    const float* bp = bias + bx * 128 + tx * 8;
#pragma unroll
    for (int j = 0; j < 8; j++) bb[j] = bp[j];
#pragma unroll
    for (int rp = 0; rp < 4; rp++) {
#pragma unroll
        for (int par = 0; par < 2; par++) {
            int row = by * 128 + ty * 8 + 2 * rp + par;
            float4 c0 = make_float4(acc[rp][0].f[par] + bb[0], acc[rp][1].f[par] + bb[1],
                                    acc[rp][2].f[par] + bb[2], acc[rp][3].f[par] + bb[3]);
            float4 c1 = make_float4(acc[rp][4].f[par] + bb[4], acc[rp][5].f[par] + bb[5],
                                    acc[rp][6].f[par] + bb[6], acc[rp][7].f[par] + bb[7]);
            float* Cp = C + (size_t)row * N + bx * 128 + tx * 8;
            *(float4*)Cp = c0;
            *(float4*)(Cp + 4) = c1;
        }
    }
}

// ---------------- flash attention (pass 1 only, P cached to global) ----------------
#define QT_S 130
#define KT_S 81
#define VS_S 81
#define PT_S 130
#define OFF_KT (64 * QT_S)
#define OFF_VS (OFF_KT + 64 * KT_S)
#define OFF_PT (OFF_VS + 64 * VS_S)
#define FLASH_SM_FLOATS (OFF_PT + 64 * PT_S)   // 27008 floats = 108032 B

__global__ __launch_bounds__(256, 2) void flash_kernel() {
    extern __shared__ float sm[];
    float* Qt = sm;                // [d=64][i=128] stride 130 (scaled Q, transposed)
    float* Kt = sm + OFF_KT;       // [d=64][sw(m=64)] stride 81
    float* Vs = sm + OFF_VS;       // [m=64][sw(d=64)] stride 81
    float* Pt = sm + OFF_PT;       // [m=64][i=128] stride 130

    const int tid = threadIdx.x;
    const int tx = tid & 15;       // cols: 4 per thread
    const int ty = tid >> 4;       // rows: 8 per thread
    const int qt = blockIdx.x;
    const int bh = blockIdx.y;
    const int b = bh >> 4, h = bh & 15;

    const float* base = g_qkv + (size_t)b * SEQ * QKVC + h * (3 * DK);

    // load Q tile (scaled), transposed
#pragma unroll
    for (int it = 0; it < 8; it++) {
        int f = tid + it * 256;
        int r = f >> 4;
        int dg = (f & 15) * 4;
        float4 v = *(const float4*)(base + (size_t)(qt * QB + r) * QKVC + dg);
        Qt[(dg + 0) * QT_S + r] = v.x * 0.125f;
        Qt[(dg + 1) * QT_S + r] = v.y * 0.125f;
        Qt[(dg + 2) * QT_S + r] = v.z * 0.125f;
        Qt[(dg + 3) * QT_S + r] = v.w * 0.125f;
    }

    float m_i[8], l_i[8];
    F2U o[4][4];
#pragma unroll
    for (int r = 0; r < 8; r++) { m_i[r] = -1e30f; l_i[r] = 0.0f; }
#pragma unroll
    for (int rp = 0; rp < 4; rp++)
#pragma unroll
        for (int j = 0; j < 4; j++) { o[rp][j].f[0] = 0.0f; o[rp][j].f[1] = 0.0f; }
    __syncthreads();

    for (int t = 0; t < NKT; t++) {
        // load K (transposed, swizzled) + V (swizzled)
#pragma unroll
        for (int it = 0; it < 4; it++) {
            int f = tid + it * 256;
            int m = f >> 4;
            int c = f & 15;
            int dg = c * 4;
            const float* rowp = base + (size_t)(t * KT + m) * QKVC;
            float4 kv = *(const float4*)(rowp + DK + dg);
            float4 vv = *(const float4*)(rowp + 2 * DK + dg);
            int swm = m + (m >> 2);
            Kt[(dg + 0) * KT_S + swm] = kv.x;
            Kt[(dg + 1) * KT_S + swm] = kv.y;
            Kt[(dg + 2) * KT_S + swm] = kv.z;
            Kt[(dg + 3) * KT_S + swm] = kv.w;
            float* vrow = &Vs[m * VS_S + 5 * c];
            vrow[0] = vv.x; vrow[1] = vv.y; vrow[2] = vv.z; vrow[3] = vv.w;
        }
        __syncthreads();

        // S = Q K^T  (f32x2, pairs over rows)
        F2U sa[4][4];
#pragma unroll
        for (int rp = 0; rp < 4; rp++)
#pragma unroll
            for (int j = 0; j < 4; j++) { sa[rp][j].f[0] = 0.0f; sa[rp][j].f[1] = 0.0f; }

#pragma unroll 8
        for (int d = 0; d < 64; d++) {
            F2U a[4];
#pragma unroll
            for (int rp = 0; rp < 4; rp++)
                a[rp].f2 = *(const float2*)&Qt[d * QT_S + ty * 8 + 2 * rp];
#pragma unroll
            for (int j = 0; j < 4; j++) {
                float bv = Kt[d * KT_S + 5 * tx + j];
                F2U bd; bd.f[0] = bv; bd.f[1] = bv;
#pragma unroll
                for (int rp = 0; rp < 4; rp++) fma2(sa[rp][j], a[rp], bd);
            }
        }

        // online softmax (row ops over 16 lanes)
        float s[8][4];
#pragma unroll
        for (int rp = 0; rp < 4; rp++)
#pragma unroll
            for (int j = 0; j < 4; j++) {
                s[2 * rp + 0][j] = sa[rp][j].f[0];
                s[2 * rp + 1][j] = sa[rp][j].f[1];
            }
        float corr[8];
#pragma unroll
        for (int r = 0; r < 8; r++) {
            float mx = fmaxf(fmaxf(s[r][0], s[r][1]), fmaxf(s[r][2], s[r][3]));
#pragma unroll
            for (int off = 8; off >= 1; off >>= 1)
                mx = fmaxf(mx, __shfl_xor_sync(0xffffffffu, mx, off, 16));
            float mnew = fmaxf(m_i[r], mx);
            corr[r] = __expf(m_i[r] - mnew);
            float rs = 0.0f;
#pragma unroll
            for (int j = 0; j < 4; j++) {
                s[r][j] = __expf(s[r][j] - mnew);
                rs += s[r][j];
            }
#pragma unroll
            for (int off = 8; off >= 1; off >>= 1)
                rs += __shfl_xor_sync(0xffffffffu, rs, off, 16);
            l_i[r] = l_i[r] * corr[r] + rs;
            m_i[r] = mnew;
        }

        // cache P (bf16) + running max to global for the colsum pass
        {
            size_t pb = (((size_t)(bh * NKT + t) * SEQ) + qt * QB + ty * 8) * KT + tx * 4;
#pragma unroll
            for (int r = 0; r < 8; r++) {
                __nv_bfloat162 h0 = __floats2bfloat162_rn(s[r][0], s[r][1]);
                __nv_bfloat162 h1 = __floats2bfloat162_rn(s[r][2], s[r][3]);
                *(__nv_bfloat162*)&g_p[pb + (size_t)r * KT] = h0;
                *(__nv_bfloat162*)&g_p[pb + (size_t)r * KT + 2] = h1;
            }
            if (tx == 0) {
                size_t mb = (size_t)(bh * NKT + t) * SEQ + qt * QB + ty * 8;
#pragma unroll
                for (int r = 0; r < 8; r++) g_mt[mb + r] = m_i[r];
            }
        }

        // rescale O by corr (packed)
#pragma unroll
        for (int rp = 0; rp < 4; rp++) {
            F2U c2; c2.f[0] = corr[2 * rp]; c2.f[1] = corr[2 * rp + 1];
#pragma unroll
            for (int j = 0; j < 4; j++) mul2(o[rp][j], c2);
        }

        // write P transposed to smem
#pragma unroll
        for (int j = 0; j < 4; j++)
#pragma unroll
            for (int rp = 0; rp < 4; rp++) {
                F2U pr; pr.f[0] = s[2 * rp][j]; pr.f[1] = s[2 * rp + 1][j];
                *(float2*)&Pt[(tx * 4 + j) * PT_S + ty * 8 + 2 * rp] = pr.f2;
            }
        __syncthreads();

        // O += P V
#pragma unroll 8
        for (int m = 0; m < 64; m++) {
            F2U p[4];
#pragma unroll
            for (int rp = 0; rp < 4; rp++)
                p[rp].f2 = *(const float2*)&Pt[m * PT_S + ty * 8 + 2 * rp];
#pragma unroll
            for (int j = 0; j < 4; j++) {
                float vv = Vs[m * VS_S + 5 * tx + j];
                F2U vd; vd.f[0] = vv; vd.f[1] = vv;
#pragma unroll
                for (int rp = 0; rp < 4; rp++) fma2(o[rp][j], p[rp], vd);
            }
        }
        __syncthreads();
    }

    // epilogue: normalized context in (B, N, H*dk)
    float inv[8];
#pragma unroll
    for (int r = 0; r < 8; r++) inv[r] = 1.0f / l_i[r];
#pragma unroll
    for (int rp = 0; rp < 4; rp++)
#pragma unroll
        for (int par = 0; par < 2; par++) {
            int row = qt * QB + ty * 8 + 2 * rp + par;
            float iv = inv[2 * rp + par];
            float4 ov = make_float4(o[rp][0].f[par] * iv, o[rp][1].f[par] * iv,
                                    o[rp][2].f[par] * iv, o[rp][3].f[par] * iv);
            *(float4*)&g_ctx[(size_t)(b * SEQ + row) * DMODEL + h * DK + tx * 4] = ov;
        }
    if (tx == 0) {
        size_t rb = (size_t)bh * SEQ + qt * QB + ty * 8;
#pragma unroll
        for (int r = 0; r < 8; r++) {
            g_mf[rb + r] = m_i[r];
            g_il[rb + r] = inv[r];
        }
    }
}

// ---------------- colsum over cached P ----------------
__global__ __launch_bounds__(256) void colsum_kernel() {
    const int kt = blockIdx.x, bh = blockIdx.y, b = bh >> 4;
    const int tid = threadIdx.x, tx = tid & 15, ty = tid >> 4;
    __shared__ float red[16][68];

    float c0 = 0.f, c1 = 0.f, c2 = 0.f, c3 = 0.f;
    const size_t strip = (size_t)(bh * NKT + kt) * SEQ;
    const float* mtp = g_mt + strip;
    const float* mfp = g_mf + (size_t)bh * SEQ;
    const float* ilp = g_il + (size_t)bh * SEQ;

    for (int r = ty; r < SEQ; r += 16) {
        float f = __expf(mtp[r] - mfp[r]) * ilp[r];
        const __nv_bfloat16* pp = g_p + (strip + r) * KT + tx * 4;
        __nv_bfloat162 pa = *(const __nv_bfloat162*)pp;
        __nv_bfloat162 pb = *(const __nv_bfloat162*)(pp + 2);
        float2 fa = __bfloat1622float2(pa);
        float2 fb = __bfloat1622float2(pb);
        c0 += f * fa.x; c1 += f * fa.y; c2 += f * fb.x; c3 += f * fb.y;
    }
    red[ty][tx * 4 + 0] = c0;
    red[ty][tx * 4 + 1] = c1;
    red[ty][tx * 4 + 2] = c2;
    red[ty][tx * 4 + 3] = c3;
    __syncthreads();
    if (tid < 64) {
        float ssum = 0.0f;
#pragma unroll
        for (int y = 0; y < 16; y++) ssum += red[y][tid];
        atomicAdd(&g_colsum[b * SEQ + kt * KT + tid], ssum);
    }
}

// ---------------- launch ----------------
extern "C" void kernel_launch(void* const* d_in, const int* in_sizes, int n_in,
                              void* d_out, int out_size) {
    const float* x     = (const float*)d_in[0];
    const float* w_qkv = (const float*)d_in[1];
    const float* b_qkv = (const float*)d_in[2];
    const float* w_out = (const float*)d_in[3];
    const float* b_out = (const float*)d_in[4];
    float* out = (float*)d_out;

    float *qkv_p, *ctx_p;
    cudaGetSymbolAddress((void**)&qkv_p, g_qkv);
    cudaGetSymbolAddress((void**)&ctx_p, g_ctx);

    const int flash_smem = FLASH_SM_FLOATS * (int)sizeof(float);
    cudaFuncSetAttribute(flash_kernel,
                         cudaFuncAttributeMaxDynamicSharedMemorySize, flash_smem);

    zero_colsum_kernel<<<(BATCH * SEQ + 255) / 256, 256>>>();

    // QKV projection
    gemm_f32x2<<<dim3(QKVC / 128, ROWS / 128), 256>>>(
        x, w_qkv, b_qkv, qkv_p, QKVC, DMODEL);

    // flash attention (single pass, P cached)
    flash_kernel<<<dim3(SEQ / QB, BATCH * NHEADS), 256, flash_smem>>>();

    // colsum for attn_mean
    colsum_kernel<<<dim3(NKT, BATCH * NHEADS), 256>>>();

    // output projection
    gemm_f32x2<<<dim3(DMODEL / 128, ROWS / 128), 256>>>(
        ctx_p, w_out, b_out, out, DMODEL, DMODEL);

    finalize_mean_kernel<<<(BATCH * SEQ + 255) / 256, 256>>>(
        out + (size_t)ROWS * DMODEL);
}

// round 4
// speedup vs baseline: 3.1744x; 1.3430x over previous
#include <cuda_runtime.h>
#include <cuda_bf16.h>
#include <math.h>
#include <stdint.h>

#define NHEADS 16
#define SEQ    2048
#define DMODEL 1024
#define BATCH  2
#define DK     64
#define QKVC   (3 * DMODEL)
#define ROWS   (BATCH * SEQ)
#define NKT    (SEQ / 64)
#define QB     128
#define KT     64

// ---------------- scratch ----------------
__device__ float g_qkv[(size_t)ROWS * QKVC];
__device__ float g_ctx[(size_t)ROWS * DMODEL];
__device__ float g_colsum[BATCH * SEQ];
__device__ __nv_bfloat16 g_p[(size_t)BATCH * NHEADS * NKT * SEQ * KT];
__device__ float g_mt[(size_t)BATCH * NHEADS * NKT * SEQ];
__device__ float g_mf[BATCH * NHEADS * SEQ];
__device__ float g_il[BATCH * NHEADS * SEQ];

// ---------------- tf32 mma helpers ----------------
__device__ __forceinline__ uint32_t cvt_tf32(float x) {
    uint32_t r;
    asm("cvt.rna.tf32.f32 %0, %1;" : "=r"(r) : "f"(x));
    return r;
}
__device__ __forceinline__ void split_tf32(float x, uint32_t& hi, uint32_t& lo) {
    hi = cvt_tf32(x);
    lo = cvt_tf32(x - __uint_as_float(hi));
}
__device__ __forceinline__ void mma_tf32(float4& c, const uint32_t a[4],
                                         uint32_t b0, uint32_t b1) {
    asm volatile(
        "mma.sync.aligned.m16n8k8.row.col.f32.tf32.tf32.f32 "
        "{%0,%1,%2,%3}, {%4,%5,%6,%7}, {%8,%9}, {%0,%1,%2,%3};"
        : "+f"(c.x), "+f"(c.y), "+f"(c.z), "+f"(c.w)
        : "r"(a[0]), "r"(a[1]), "r"(a[2]), "r"(a[3]), "r"(b0), "r"(b1));
}

// ---------------- cp.async helpers ----------------
__device__ __forceinline__ void cp16(uint32_t dst, const void* src) {
    asm volatile("cp.async.cg.shared.global [%0], [%1], 16;" :: "r"(dst), "l"(src));
}
__device__ __forceinline__ void cp_commit() {
    asm volatile("cp.async.commit_group;");
}
__device__ __forceinline__ void cp_wait1() {
    asm volatile("cp.async.wait_group 1;");
}
__device__ __forceinline__ void cp_wait0() {
    asm volatile("cp.async.wait_group 0;");
}

// ---------------- misc kernels ----------------
__global__ void zero_colsum_kernel() {
    int i = blockIdx.x * blockDim.x + threadIdx.x;
    if (i < BATCH * SEQ) g_colsum[i] = 0.0f;
}
__global__ void finalize_mean_kernel(float* __restrict__ out_mean) {
    int i = blockIdx.x * blockDim.x + threadIdx.x;
    if (i < BATCH * SEQ)
        out_mean[i] = g_colsum[i] * (1.0f / (float)(NHEADS * SEQ));
}

// ---------------- dense GEMM, split-tf32 mma, 128x128x16 ----------------
#define GASW 20
#define GBSW 136

__global__ __launch_bounds__(256) void gemm_tc(
    const float* __restrict__ A, const float* __restrict__ B,
    const float* __restrict__ bias, float* __restrict__ C,
    int N, int K)
{
    __shared__ float As[2][128 * GASW];
    __shared__ float Bs[2][16 * GBSW];

    const int tid = threadIdx.x, lane = tid & 31, wid = tid >> 5;
    const int gid = lane >> 2, tig = lane & 3;
    const int wm = wid & 1, wn = wid >> 1;
    const int bx = blockIdx.x, by = blockIdx.y;

    const int am = tid >> 1, ak = (tid & 1) * 8;
    const int bk = tid >> 4, bn = (tid & 15) * 8;
    const float* Ap = A + (size_t)(by * 128 + am) * K + ak;
    const float* Bp = B + (size_t)bk * N + bx * 128 + bn;

    {
        float4 a0 = *(const float4*)Ap, a1 = *(const float4*)(Ap + 4);
        float4 b0 = *(const float4*)Bp, b1 = *(const float4*)(Bp + 4);
        *(float4*)&As[0][am * GASW + ak] = a0;
        *(float4*)&As[0][am * GASW + ak + 4] = a1;
        *(float4*)&Bs[0][bk * GBSW + bn] = b0;
        *(float4*)&Bs[0][bk * GBSW + bn + 4] = b1;
    }
    __syncthreads();

    float4 acc[4][4];
#pragma unroll
    for (int mt = 0; mt < 4; mt++)
#pragma unroll
        for (int nt = 0; nt < 4; nt++) acc[mt][nt] = make_float4(0.f, 0.f, 0.f, 0.f);

    const int nT = K / 16;
    for (int tk = 0; tk < nT; tk++) {
        const int cur = tk & 1;
        float4 na0, na1, nb0, nb1;
        if (tk + 1 < nT) {
            na0 = *(const float4*)(Ap + (tk + 1) * 16);
            na1 = *(const float4*)(Ap + (tk + 1) * 16 + 4);
            nb0 = *(const float4*)(Bp + (size_t)(tk + 1) * 16 * N);
            nb1 = *(const float4*)(Bp + (size_t)(tk + 1) * 16 * N + 4);
        }
#pragma unroll
        for (int kk = 0; kk < 2; kk++) {
            const int k0 = kk * 8;
            uint32_t ah[4][4], al[4][4];
#pragma unroll
            for (int mt = 0; mt < 4; mt++) {
                const int r = wm * 64 + mt * 16;
                float v0 = As[cur][(r + gid) * GASW + k0 + tig];
                float v1 = As[cur][(r + gid + 8) * GASW + k0 + tig];
                float v2 = As[cur][(r + gid) * GASW + k0 + tig + 4];
                float v3 = As[cur][(r + gid + 8) * GASW + k0 + tig + 4];
                split_tf32(v0, ah[mt][0], al[mt][0]);
                split_tf32(v1, ah[mt][1], al[mt][1]);
                split_tf32(v2, ah[mt][2], al[mt][2]);
                split_tf32(v3, ah[mt][3], al[mt][3]);
            }
#pragma unroll
            for (int nt = 0; nt < 4; nt++) {
                const int c = wn * 32 + nt * 8 + gid;
                float w0 = Bs[cur][(k0 + tig) * GBSW + c];
                float w1 = Bs[cur][(k0 + tig + 4) * GBSW + c];
                uint32_t bh0, bl0, bh1, bl1;
                split_tf32(w0, bh0, bl0);
                split_tf32(w1, bh1, bl1);
#pragma unroll
                for (int mt = 0; mt < 4; mt++) {
                    mma_tf32(acc[mt][nt], ah[mt], bh0, bh1);
                    mma_tf32(acc[mt][nt], ah[mt], bl0, bl1);
                    mma_tf32(acc[mt][nt], al[mt], bh0, bh1);
                }
            }
        }
        if (tk + 1 < nT) {
            const int nxt = cur ^ 1;
            *(float4*)&As[nxt][am * GASW + ak] = na0;
            *(float4*)&As[nxt][am * GASW + ak + 4] = na1;
            *(float4*)&Bs[nxt][bk * GBSW + bn] = nb0;
            *(float4*)&Bs[nxt][bk * GBSW + bn + 4] = nb1;
        }
        __syncthreads();
    }

    // epilogue + bias
#pragma unroll
    for (int mt = 0; mt < 4; mt++) {
        int row = by * 128 + wm * 64 + mt * 16 + gid;
#pragma unroll
        for (int nt = 0; nt < 4; nt++) {
            int col = bx * 128 + wn * 32 + nt * 8 + 2 * tig;
            float bv0 = bias[col], bv1 = bias[col + 1];
            *(float2*)&C[(size_t)row * N + col] =
                make_float2(acc[mt][nt].x + bv0, acc[mt][nt].y + bv1);
            *(float2*)&C[(size_t)(row + 8) * N + col] =
                make_float2(acc[mt][nt].z + bv0, acc[mt][nt].w + bv1);
        }
    }
}

// ---------------- flash attention, tf32 mma ----------------
#define KSW 72
#define PSW 72
#define FLASH_SMEM_BYTES ((4 * 64 * KSW + QB * PSW) * 4)

__global__ __launch_bounds__(256) void flash_tc() {
    extern __shared__ float sm[];
    float* KSb[2] = { sm, sm + 64 * KSW };
    float* VSb[2] = { sm + 2 * 64 * KSW, sm + 3 * 64 * KSW };
    float* PS = sm + 4 * 64 * KSW;   // [128][72]

    const int tid = threadIdx.x, lane = tid & 31, wid = tid >> 5;
    const int gid = lane >> 2, tig = lane & 3;
    const int qt = blockIdx.x, bh = blockIdx.y;
    const int b = bh >> 4, h = bh & 15;

    const float* base = g_qkv + (size_t)b * SEQ * QKVC + h * (3 * DK);

    uint32_t ks_u[2], vs_u[2];
    ks_u[0] = (uint32_t)__cvta_generic_to_shared(KSb[0]);
    ks_u[1] = (uint32_t)__cvta_generic_to_shared(KSb[1]);
    vs_u[0] = (uint32_t)__cvta_generic_to_shared(VSb[0]);
    vs_u[1] = (uint32_t)__cvta_generic_to_shared(VSb[1]);

    // prefetch K/V tile 0
#pragma unroll
    for (int it = 0; it < 4; it++) {
        int f = tid + it * 256;
        int m = f >> 4, dg = (f & 15) * 4;
        const float* rp = base + (size_t)m * QKVC + DK + dg;
        cp16(ks_u[0] + (m * KSW + dg) * 4, rp);
        cp16(vs_u[0] + (m * KSW + dg) * 4, rp + DK);
    }
    cp_commit();

    // stage Q (scaled) into PS, then pull A-fragments into registers
#pragma unroll
    for (int it = 0; it < 8; it++) {
        int f = tid + it * 256;
        int r = f >> 4, dg = (f & 15) * 4;
        float4 v = *(const float4*)(base + (size_t)(qt * QB + r) * QKVC + dg);
        v.x *= 0.125f; v.y *= 0.125f; v.z *= 0.125f; v.w *= 0.125f;
        *(float4*)&PS[r * PSW + dg] = v;
    }
    __syncthreads();

    const int r0 = wid * 16 + gid;
    uint32_t q[8][4];
#pragma unroll
    for (int kt = 0; kt < 8; kt++) {
        q[kt][0] = cvt_tf32(PS[r0 * PSW + kt * 8 + tig]);
        q[kt][1] = cvt_tf32(PS[(r0 + 8) * PSW + kt * 8 + tig]);
        q[kt][2] = cvt_tf32(PS[r0 * PSW + kt * 8 + tig + 4]);
        q[kt][3] = cvt_tf32(PS[(r0 + 8) * PSW + kt * 8 + tig + 4]);
    }

    float m0 = -1e30f, m1 = -1e30f, l0 = 0.f, l1 = 0.f;
    float4 o[8];
#pragma unroll
    for (int nt = 0; nt < 8; nt++) o[nt] = make_float4(0.f, 0.f, 0.f, 0.f);

    for (int t = 0; t < NKT; t++) {
        const int cur = t & 1;
        __syncthreads();    // all reads of PS / buf cur^1 from prev iter done
        if (t + 1 < NKT) {
#pragma unroll
            for (int it = 0; it < 4; it++) {
                int f = tid + it * 256;
                int m = f >> 4, dg = (f & 15) * 4;
                const float* rp = base + (size_t)((t + 1) * KT + m) * QKVC + DK + dg;
                cp16(ks_u[cur ^ 1] + (m * KSW + dg) * 4, rp);
                cp16(vs_u[cur ^ 1] + (m * KSW + dg) * 4, rp + DK);
            }
            cp_commit();
            cp_wait1();
        } else {
            cp_wait0();
        }
        __syncthreads();    // buf cur visible to all

        const float* KS = KSb[cur];
        const float* VS = VSb[cur];

        // S = Q K^T
        float4 s[8];
#pragma unroll
        for (int nt = 0; nt < 8; nt++) s[nt] = make_float4(0.f, 0.f, 0.f, 0.f);
#pragma unroll
        for (int kt = 0; kt < 8; kt++) {
#pragma unroll
            for (int nt = 0; nt < 8; nt++) {
                uint32_t b0 = cvt_tf32(KS[(nt * 8 + gid) * KSW + kt * 8 + tig]);
                uint32_t b1 = cvt_tf32(KS[(nt * 8 + gid) * KSW + kt * 8 + tig + 4]);
                mma_tf32(s[nt], q[kt], b0, b1);
            }
        }

        // online softmax: rows r0 (x,y) and r0+8 (z,w)
        float mx0 = -1e30f, mx1 = -1e30f;
#pragma unroll
        for (int nt = 0; nt < 8; nt++) {
            mx0 = fmaxf(mx0, fmaxf(s[nt].x, s[nt].y));
            mx1 = fmaxf(mx1, fmaxf(s[nt].z, s[nt].w));
        }
        mx0 = fmaxf(mx0, __shfl_xor_sync(0xffffffffu, mx0, 1));
        mx0 = fmaxf(mx0, __shfl_xor_sync(0xffffffffu, mx0, 2));
        mx1 = fmaxf(mx1, __shfl_xor_sync(0xffffffffu, mx1, 1));
        mx1 = fmaxf(mx1, __shfl_xor_sync(0xffffffffu, mx1, 2));
        float nm0 = fmaxf(m0, mx0), nm1 = fmaxf(m1, mx1);
        float c0 = __expf(m0 - nm0), c1 = __expf(m1 - nm1);
        float rs0 = 0.f, rs1 = 0.f;
#pragma unroll
        for (int nt = 0; nt < 8; nt++) {
            s[nt].x = __expf(s[nt].x - nm0);
            s[nt].y = __expf(s[nt].y - nm0);
            s[nt].z = __expf(s[nt].z - nm1);
            s[nt].w = __expf(s[nt].w - nm1);
            rs0 += s[nt].x + s[nt].y;
            rs1 += s[nt].z + s[nt].w;
        }
        rs0 += __shfl_xor_sync(0xffffffffu, rs0, 1);
        rs0 += __shfl_xor_sync(0xffffffffu, rs0, 2);
        rs1 += __shfl_xor_sync(0xffffffffu, rs1, 1);
        rs1 += __shfl_xor_sync(0xffffffffu, rs1, 2);
        l0 = l0 * c0 + rs0;
        l1 = l1 * c1 + rs1;
        m0 = nm0; m1 = nm1;

        // rescale O
#pragma unroll
        for (int nt = 0; nt < 8; nt++) {
            o[nt].x *= c0; o[nt].y *= c0;
            o[nt].z *= c1; o[nt].w *= c1;
        }

        // P -> smem
#pragma unroll
        for (int nt = 0; nt < 8; nt++) {
            *(float2*)&PS[r0 * PSW + nt * 8 + 2 * tig] = make_float2(s[nt].x, s[nt].y);
            *(float2*)&PS[(r0 + 8) * PSW + nt * 8 + 2 * tig] = make_float2(s[nt].z, s[nt].w);
        }
        if (tig == 0) {
            size_t mb = (size_t)(bh * NKT + t) * SEQ + qt * QB;
            g_mt[mb + r0] = m0;
            g_mt[mb + r0 + 8] = m1;
        }
        __syncthreads();    // PS complete

        // coalesced bf16 P cache store
        {
            size_t strip = (size_t)(bh * NKT + t) * SEQ + qt * QB;
#pragma unroll
            for (int it = 0; it < 16; it++) {
                int f = tid + it * 256;
                int i = f >> 5, mp = (f & 31) * 2;
                float2 p2 = *(const float2*)&PS[i * PSW + mp];
                *(__nv_bfloat162*)&g_p[(strip + i) * KT + mp] =
                    __floats2bfloat162_rn(p2.x, p2.y);
            }
        }

        // O += P V
#pragma unroll
        for (int kt = 0; kt < 8; kt++) {
            uint32_t a[4];
            a[0] = cvt_tf32(PS[r0 * PSW + kt * 8 + tig]);
            a[1] = cvt_tf32(PS[(r0 + 8) * PSW + kt * 8 + tig]);
            a[2] = cvt_tf32(PS[r0 * PSW + kt * 8 + tig + 4]);
            a[3] = cvt_tf32(PS[(r0 + 8) * PSW + kt * 8 + tig + 4]);
#pragma unroll
            for (int nt = 0; nt < 8; nt++) {
                uint32_t b0 = cvt_tf32(VS[(kt * 8 + tig) * KSW + nt * 8 + gid]);
                uint32_t b1 = cvt_tf32(VS[(kt * 8 + tig + 4) * KSW + nt * 8 + gid]);
                mma_tf32(o[nt], a, b0, b1);
            }
        }
    }

    // epilogue
    float i0 = 1.0f / l0, i1 = 1.0f / l1;
    size_t cb = ((size_t)b * SEQ + qt * QB) * DMODEL + h * DK;
#pragma unroll
    for (int nt = 0; nt < 8; nt++) {
        int col = nt * 8 + 2 * tig;
        *(float2*)&g_ctx[cb + (size_t)r0 * DMODEL + col] =
            make_float2(o[nt].x * i0, o[nt].y * i0);
        *(float2*)&g_ctx[cb + (size_t)(r0 + 8) * DMODEL + col] =
            make_float2(o[nt].z * i1, o[nt].w * i1);
    }
    if (tig == 0) {
        size_t rb = (size_t)bh * SEQ + qt * QB;
        g_mf[rb + r0] = m0;  g_il[rb + r0] = i0;
        g_mf[rb + r0 + 8] = m1;  g_il[rb + r0 + 8] = i1;
    }
}

// ---------------- colsum over cached P ----------------
__global__ __launch_bounds__(256) void colsum_kernel() {
    const int kt = blockIdx.x, bh = blockIdx.y, b = bh >> 4;
    const int tid = threadIdx.x, tx = tid & 15, ty = tid >> 4;
    __shared__ float red[16][68];

    float c0 = 0.f, c1 = 0.f, c2 = 0.f, c3 = 0.f;
    const size_t strip = (size_t)(bh * NKT + kt) * SEQ;
    const float* mtp = g_mt + strip;
    const float* mfp = g_mf + (size_t)bh * SEQ;
    const float* ilp = g_il + (size_t)bh * SEQ;

    for (int r = ty; r < SEQ; r += 16) {
        float f = __expf(mtp[r] - mfp[r]) * ilp[r];
        const __nv_bfloat16* pp = g_p + (strip + r) * KT + tx * 4;
        __nv_bfloat162 pa = *(const __nv_bfloat162*)pp;
        __nv_bfloat162 pb = *(const __nv_bfloat162*)(pp + 2);
        float2 fa = __bfloat1622float2(pa);
        float2 fb = __bfloat1622float2(pb);
        c0 += f * fa.x; c1 += f * fa.y; c2 += f * fb.x; c3 += f * fb.y;
    }
    red[ty][tx * 4 + 0] = c0;
    red[ty][tx * 4 + 1] = c1;
    red[ty][tx * 4 + 2] = c2;
    red[ty][tx * 4 + 3] = c3;
    __syncthreads();
    if (tid < 64) {
        float ssum = 0.0f;
#pragma unroll
        for (int y = 0; y < 16; y++) ssum += red[y][tid];
        atomicAdd(&g_colsum[b * SEQ + kt * KT + tid], ssum);
    }
}

// ---------------- launch ----------------
extern "C" void kernel_launch(void* const* d_in, const int* in_sizes, int n_in,
                              void* d_out, int out_size) {
    const float* x     = (const float*)d_in[0];
    const float* w_qkv = (const float*)d_in[1];
    const float* b_qkv = (const float*)d_in[2];
    const float* w_out = (const float*)d_in[3];
    const float* b_out = (const float*)d_in[4];
    float* out = (float*)d_out;

    float *qkv_p, *ctx_p;
    cudaGetSymbolAddress((void**)&qkv_p, g_qkv);
    cudaGetSymbolAddress((void**)&ctx_p, g_ctx);

    cudaFuncSetAttribute(flash_tc,
                         cudaFuncAttributeMaxDynamicSharedMemorySize,
                         FLASH_SMEM_BYTES);

    zero_colsum_kernel<<<(BATCH * SEQ + 255) / 256, 256>>>();

    // QKV projection (split tf32)
    gemm_tc<<<dim3(QKVC / 128, ROWS / 128), 256>>>(
        x, w_qkv, b_qkv, qkv_p, QKVC, DMODEL);

    // flash attention (tensor core)
    flash_tc<<<dim3(SEQ / QB, BATCH * NHEADS), 256, FLASH_SMEM_BYTES>>>();

    // colsum for attn_mean
    colsum_kernel<<<dim3(NKT, BATCH * NHEADS), 256>>>();

    // output projection (split tf32)
    gemm_tc<<<dim3(DMODEL / 128, ROWS / 128), 256>>>(
        ctx_p, w_out, b_out, out, DMODEL, DMODEL);

    finalize_mean_kernel<<<(BATCH * SEQ + 255) / 256, 256>>>(
        out + (size_t)ROWS * DMODEL);
}

// round 7
// speedup vs baseline: 3.8515x; 1.2133x over previous
#include <cuda_runtime.h>
#include <cuda_bf16.h>
#include <math.h>
#include <stdint.h>

#define NHEADS 16
#define SEQ    2048
#define DMODEL 1024
#define BATCH  2
#define DK     64
#define QKVC   (3 * DMODEL)
#define ROWS   (BATCH * SEQ)
#define NKT    (SEQ / 64)
#define QB     128
#define KT     64

// ---------------- scratch ----------------
__device__ float g_qkv[(size_t)ROWS * QKVC];            // tf32-rounded qkv
__device__ float g_colsum[BATCH * SEQ];
__device__ __nv_bfloat16 g_p[(size_t)BATCH * NHEADS * NKT * SEQ * KT];
__device__ float g_mt[(size_t)BATCH * NHEADS * NKT * SEQ];
__device__ float g_mf[BATCH * NHEADS * SEQ];
__device__ float g_il[BATCH * NHEADS * SEQ];
// bf16 split operands
__device__ __nv_bfloat16 g_xhi[(size_t)ROWS * DMODEL];
__device__ __nv_bfloat16 g_xlo[(size_t)ROWS * DMODEL];
__device__ __nv_bfloat16 g_wqh[(size_t)DMODEL * QKVC];
__device__ __nv_bfloat16 g_wql[(size_t)DMODEL * QKVC];
__device__ __nv_bfloat16 g_woh[(size_t)DMODEL * DMODEL];
__device__ __nv_bfloat16 g_wol[(size_t)DMODEL * DMODEL];
__device__ __nv_bfloat16 g_chi[(size_t)ROWS * DMODEL];
__device__ __nv_bfloat16 g_clo[(size_t)ROWS * DMODEL];

// ---------------- helpers ----------------
__device__ __forceinline__ uint32_t cvt_tf32(float x) {
    uint32_t r;
    asm("cvt.rna.tf32.f32 %0, %1;" : "=r"(r) : "f"(x));
    return r;
}
__device__ __forceinline__ float tf32f(float x) { return __uint_as_float(cvt_tf32(x)); }

__device__ __forceinline__ void bsplit(float v, __nv_bfloat16& h, __nv_bfloat16& l) {
    h = __float2bfloat16(v);
    l = __float2bfloat16(v - __bfloat162float(h));
}

__device__ __forceinline__ void mma_tf32(float4& c, const uint32_t a[4],
                                         uint32_t b0, uint32_t b1) {
    asm volatile(
        "mma.sync.aligned.m16n8k8.row.col.f32.tf32.tf32.f32 "
        "{%0,%1,%2,%3}, {%4,%5,%6,%7}, {%8,%9}, {%0,%1,%2,%3};"
        : "+f"(c.x), "+f"(c.y), "+f"(c.z), "+f"(c.w)
        : "r"(a[0]), "r"(a[1]), "r"(a[2]), "r"(a[3]), "r"(b0), "r"(b1));
}
__device__ __forceinline__ void mma_bf16(float4& c, const uint32_t a[4],
                                         uint32_t b0, uint32_t b1) {
    asm volatile(
        "mma.sync.aligned.m16n8k16.row.col.f32.bf16.bf16.f32 "
        "{%0,%1,%2,%3}, {%4,%5,%6,%7}, {%8,%9}, {%0,%1,%2,%3};"
        : "+f"(c.x), "+f"(c.y), "+f"(c.z), "+f"(c.w)
        : "r"(a[0]), "r"(a[1]), "r"(a[2]), "r"(a[3]), "r"(b0), "r"(b1));
}

__device__ __forceinline__ void cp16(uint32_t dst, const void* src) {
    asm volatile("cp.async.cg.shared.global [%0], [%1], 16;" :: "r"(dst), "l"(src));
}
__device__ __forceinline__ void cp_commit() { asm volatile("cp.async.commit_group;"); }
__device__ __forceinline__ void cp_wait1()  { asm volatile("cp.async.wait_group 1;"); }
__device__ __forceinline__ void cp_wait0()  { asm volatile("cp.async.wait_group 0;"); }

// ---------------- misc kernels ----------------
__global__ void zero_colsum_kernel() {
    int i = blockIdx.x * blockDim.x + threadIdx.x;
    if (i < BATCH * SEQ) g_colsum[i] = 0.0f;
}
__global__ void finalize_mean_kernel(float* __restrict__ out_mean) {
    int i = blockIdx.x * blockDim.x + threadIdx.x;
    if (i < BATCH * SEQ)
        out_mean[i] = g_colsum[i] * (1.0f / (float)(NHEADS * SEQ));
}
// split fp32 -> bf16 hi/lo (vectorized by 4)
__global__ void split4_kernel(const float4* __restrict__ src,
                              __nv_bfloat162* __restrict__ hi,
                              __nv_bfloat162* __restrict__ lo, int n4) {
    int i = blockIdx.x * blockDim.x + threadIdx.x;
    if (i >= n4) return;
    float4 v = src[i];
    __nv_bfloat16 h0, l0, h1, l1, h2, l2, h3, l3;
    bsplit(v.x, h0, l0); bsplit(v.y, h1, l1);
    bsplit(v.z, h2, l2); bsplit(v.w, h3, l3);
    __nv_bfloat162 a, b, c, d;
    a.x = h0; a.y = h1; b.x = h2; b.y = h3;
    c.x = l0; c.y = l1; d.x = l2; d.y = l3;
    hi[2 * i] = a; hi[2 * i + 1] = b;
    lo[2 * i] = c; lo[2 * i + 1] = d;
}

// ---------------- dense GEMM: bf16 3-term split, 128x128x16, dbuf ----------------
#define AKW 24   // bf16 stride of A smem rows (12 words -> conflict-free frags)
#define BKW 26   // bf16 stride of B smem rows [n][k] (13 words)
#define GEMM_SMEM_BF16 (2 * (2 * 128 * AKW + 2 * 128 * BKW))   // 25600 bf16 = 51200 B

__global__ __launch_bounds__(256) void gemm_bf16s(
    const __nv_bfloat16* __restrict__ Ahi, const __nv_bfloat16* __restrict__ Alo,
    const __nv_bfloat16* __restrict__ Bhi, const __nv_bfloat16* __restrict__ Blo,
    const float* __restrict__ bias, float* __restrict__ C,
    int N, int K, int round_out)
{
    extern __shared__ char gsm_raw[];
    __nv_bfloat16* sm = (__nv_bfloat16*)gsm_raw;
    // per buffer (12800 bf16): [Ah 3072][Al 3072][Bh 3328][Bl 3328]
    const int BUF = 12800;

    const int tid = threadIdx.x, lane = tid & 31, wid = tid >> 5;
    const int gid = lane >> 2, tig = lane & 3;
    const int wm = wid & 1, wn = wid >> 1;
    const int bx = blockIdx.x, by = blockIdx.y;

    const int am = tid >> 1, ak = (tid & 1) * 8;
    const int bk = tid >> 4, bn = (tid & 15) * 8;
    const int kw = bk >> 1, kp = bk & 1;

    const __nv_bfloat16* Agh = Ahi + (size_t)(by * 128 + am) * K + ak;
    const __nv_bfloat16* Agl = Alo + (size_t)(by * 128 + am) * K + ak;
    const __nv_bfloat16* Bgh = Bhi + (size_t)bk * N + bx * 128 + bn;
    const __nv_bfloat16* Bgl = Blo + (size_t)bk * N + bx * 128 + bn;

    // prologue: tile 0 into buf 0
    {
        uint4 a_h = *(const uint4*)Agh;
        uint4 a_l = *(const uint4*)Agl;
        uint4 b_h = *(const uint4*)Bgh;
        uint4 b_l = *(const uint4*)Bgl;
        *(uint4*)&sm[0 * BUF + am * AKW + ak] = a_h;
        *(uint4*)&sm[0 * BUF + 3072 + am * AKW + ak] = a_l;
        const __nv_bfloat16* hv = (const __nv_bfloat16*)&b_h;
        const __nv_bfloat16* lv = (const __nv_bfloat16*)&b_l;
#pragma unroll
        for (int j = 0; j < 8; j++) {
            int n = bn + j;
            int kk = ((kw + (n >> 5)) & 7) * 2 + kp;
            sm[0 * BUF + 6144 + n * BKW + kk] = hv[j];
            sm[0 * BUF + 9472 + n * BKW + kk] = lv[j];
        }
    }
    __syncthreads();

    float4 acc[4][4];
#pragma unroll
    for (int mt = 0; mt < 4; mt++)
#pragma unroll
        for (int nt = 0; nt < 4; nt++) acc[mt][nt] = make_float4(0.f, 0.f, 0.f, 0.f);

    const int nT = K / 16;
    for (int tk = 0; tk < nT; tk++) {
        const int cur = tk & 1;
        uint4 na_h, na_l, nb_h, nb_l;
        if (tk + 1 < nT) {
            int k0 = (tk + 1) * 16;
            na_h = *(const uint4*)(Agh + k0);
            na_l = *(const uint4*)(Agl + k0);
            nb_h = *(const uint4*)(Bgh + (size_t)k0 * N);
            nb_l = *(const uint4*)(Bgl + (size_t)k0 * N);
        }

        const __nv_bfloat16* Ah_s = sm + cur * BUF;
        const __nv_bfloat16* Al_s = Ah_s + 3072;
        const __nv_bfloat16* Bh_s = sm + cur * BUF + 6144;
        const __nv_bfloat16* Bl_s = Bh_s + 3328;

        uint32_t ah[4][4], al[4][4];
#pragma unroll
        for (int mt = 0; mt < 4; mt++) {
            int r = wm * 64 + mt * 16;
            ah[mt][0] = *(const uint32_t*)&Ah_s[(r + gid) * AKW + 2 * tig];
            ah[mt][1] = *(const uint32_t*)&Ah_s[(r + gid + 8) * AKW + 2 * tig];
            ah[mt][2] = *(const uint32_t*)&Ah_s[(r + gid) * AKW + 2 * tig + 8];
            ah[mt][3] = *(const uint32_t*)&Ah_s[(r + gid + 8) * AKW + 2 * tig + 8];
            al[mt][0] = *(const uint32_t*)&Al_s[(r + gid) * AKW + 2 * tig];
            al[mt][1] = *(const uint32_t*)&Al_s[(r + gid + 8) * AKW + 2 * tig];
            al[mt][2] = *(const uint32_t*)&Al_s[(r + gid) * AKW + 2 * tig + 8];
            al[mt][3] = *(const uint32_t*)&Al_s[(r + gid + 8) * AKW + 2 * tig + 8];
        }
#pragma unroll
        for (int nt = 0; nt < 4; nt++) {
            int n = wn * 32 + nt * 8 + gid;
            int k0 = 2 * ((tig + wn) & 7);
            int k1 = 2 * ((tig + 4 + wn) & 7);
            uint32_t bh0 = *(const uint32_t*)&Bh_s[n * BKW + k0];
            uint32_t bh1 = *(const uint32_t*)&Bh_s[n * BKW + k1];
            uint32_t bl0 = *(const uint32_t*)&Bl_s[n * BKW + k0];
            uint32_t bl1 = *(const uint32_t*)&Bl_s[n * BKW + k1];
#pragma unroll
            for (int mt = 0; mt < 4; mt++) {
                mma_bf16(acc[mt][nt], ah[mt], bh0, bh1);
                mma_bf16(acc[mt][nt], ah[mt], bl0, bl1);
                mma_bf16(acc[mt][nt], al[mt], bh0, bh1);
            }
        }

        if (tk + 1 < nT) {
            const int nxt = cur ^ 1;
            __syncthreads();   // all reads of nxt buffer done (it was used 2 iters ago)
            *(uint4*)&sm[nxt * BUF + am * AKW + ak] = na_h;
            *(uint4*)&sm[nxt * BUF + 3072 + am * AKW + ak] = na_l;
            const __nv_bfloat16* hv = (const __nv_bfloat16*)&nb_h;
            const __nv_bfloat16* lv = (const __nv_bfloat16*)&nb_l;
#pragma unroll
            for (int j = 0; j < 8; j++) {
                int n = bn + j;
                int kk = ((kw + (n >> 5)) & 7) * 2 + kp;
                sm[nxt * BUF + 6144 + n * BKW + kk] = hv[j];
                sm[nxt * BUF + 9472 + n * BKW + kk] = lv[j];
            }
            __syncthreads();
        }
    }

    // epilogue + bias (+ optional tf32 rounding for qkv)
#pragma unroll
    for (int mt = 0; mt < 4; mt++) {
        int row = by * 128 + wm * 64 + mt * 16 + gid;
#pragma unroll
        for (int nt = 0; nt < 4; nt++) {
            int col = bx * 128 + wn * 32 + nt * 8 + 2 * tig;
            float bv0 = bias[col], bv1 = bias[col + 1];
            float x0 = acc[mt][nt].x + bv0, x1 = acc[mt][nt].y + bv1;
            float x2 = acc[mt][nt].z + bv0, x3 = acc[mt][nt].w + bv1;
            if (round_out) {
                x0 = tf32f(x0); x1 = tf32f(x1); x2 = tf32f(x2); x3 = tf32f(x3);
            }
            *(float2*)&C[(size_t)row * N + col] = make_float2(x0, x1);
            *(float2*)&C[(size_t)(row + 8) * N + col] = make_float2(x2, x3);
        }
    }
}

// ---------------- flash attention, tf32 mma (pre-rounded inputs) ----------------
#define KSWK 76
#define VSW  72
#define PSW  76
#define OFF_KS1 (64 * KSWK)
#define OFF_VS0 (2 * 64 * KSWK)
#define OFF_VS1 (OFF_VS0 + 64 * VSW)
#define OFF_PS  (OFF_VS1 + 64 * VSW)
#define FLASH_SMEM_BYTES ((OFF_PS + QB * PSW) * 4)   // 114688 B

__global__ __launch_bounds__(256) void flash_tc() {
    extern __shared__ float fsm[];
    float* KSb[2] = { fsm, fsm + OFF_KS1 };
    float* VSb[2] = { fsm + OFF_VS0, fsm + OFF_VS1 };
    float* PS = fsm + OFF_PS;   // [128][76]

    const int tid = threadIdx.x, lane = tid & 31, wid = tid >> 5;
    const int gid = lane >> 2, tig = lane & 3;
    const int qt = blockIdx.x, bh = blockIdx.y;
    const int b = bh >> 4, h = bh & 15;

    const float* base = g_qkv + (size_t)b * SEQ * QKVC + h * (3 * DK);

    uint32_t ks_u[2], vs_u[2];
    ks_u[0] = (uint32_t)__cvta_generic_to_shared(KSb[0]);
    ks_u[1] = (uint32_t)__cvta_generic_to_shared(KSb[1]);
    vs_u[0] = (uint32_t)__cvta_generic_to_shared(VSb[0]);
    vs_u[1] = (uint32_t)__cvta_generic_to_shared(VSb[1]);

    // prefetch K/V tile 0
#pragma unroll
    for (int it = 0; it < 4; it++) {
        int f = tid + it * 256;
        int m = f >> 4, dg = (f & 15) * 4;
        const float* rp = base + (size_t)m * QKVC + DK + dg;
        cp16(ks_u[0] + (m * KSWK + dg) * 4, rp);
        cp16(vs_u[0] + (m * VSW + dg) * 4, rp + DK);
    }
    cp_commit();

    // stage Q (scaled; values stay tf32-exact since 0.125 = 2^-3)
#pragma unroll
    for (int it = 0; it < 8; it++) {
        int f = tid + it * 256;
        int r = f >> 4, dg = (f & 15) * 4;
        float4 v = *(const float4*)(base + (size_t)(qt * QB + r) * QKVC + dg);
        v.x *= 0.125f; v.y *= 0.125f; v.z *= 0.125f; v.w *= 0.125f;
        *(float4*)&PS[r * PSW + dg] = v;
    }
    __syncthreads();

    const int r0 = wid * 16 + gid;
    uint32_t q[8][4];
#pragma unroll
    for (int kt = 0; kt < 8; kt++) {
        q[kt][0] = __float_as_uint(PS[r0 * PSW + kt * 8 + tig]);
        q[kt][1] = __float_as_uint(PS[(r0 + 8) * PSW + kt * 8 + tig]);
        q[kt][2] = __float_as_uint(PS[r0 * PSW + kt * 8 + tig + 4]);
        q[kt][3] = __float_as_uint(PS[(r0 + 8) * PSW + kt * 8 + tig + 4]);
    }

    float m0 = -1e30f, m1 = -1e30f, l0 = 0.f, l1 = 0.f;
    float4 o[8];
#pragma unroll
    for (int nt = 0; nt < 8; nt++) o[nt] = make_float4(0.f, 0.f, 0.f, 0.f);

    for (int t = 0; t < NKT; t++) {
        const int cur = t & 1;
        __syncthreads();
        if (t + 1 < NKT) {
#pragma unroll
            for (int it = 0; it < 4; it++) {
                int f = tid + it * 256;
                int m = f >> 4, dg = (f & 15) * 4;
                const float* rp = base + (size_t)((t + 1) * KT + m) * QKVC + DK + dg;
                cp16(ks_u[cur ^ 1] + (m * KSWK + dg) * 4, rp);
                cp16(vs_u[cur ^ 1] + (m * VSW + dg) * 4, rp + DK);
            }
            cp_commit();
            cp_wait1();
        } else {
            cp_wait0();
        }
        __syncthreads();

        const float* KS = KSb[cur];
        const float* VS = VSb[cur];

        // S = Q K^T  (no cvt: operands pre-rounded to tf32)
        float4 s[8];
#pragma unroll
        for (int nt = 0; nt < 8; nt++) s[nt] = make_float4(0.f, 0.f, 0.f, 0.f);
#pragma unroll
        for (int kt = 0; kt < 8; kt++) {
#pragma unroll
            for (int nt = 0; nt < 8; nt++) {
                uint32_t b0 = __float_as_uint(KS[(nt * 8 + gid) * KSWK + kt * 8 + tig]);
                uint32_t b1 = __float_as_uint(KS[(nt * 8 + gid) * KSWK + kt * 8 + tig + 4]);
                mma_tf32(s[nt], q[kt], b0, b1);
            }
        }

        // online softmax
        float mx0 = -1e30f, mx1 = -1e30f;
#pragma unroll
        for (int nt = 0; nt < 8; nt++) {
            mx0 = fmaxf(mx0, fmaxf(s[nt].x, s[nt].y));
            mx1 = fmaxf(mx1, fmaxf(s[nt].z, s[nt].w));
        }
        mx0 = fmaxf(mx0, __shfl_xor_sync(0xffffffffu, mx0, 1));
        mx0 = fmaxf(mx0, __shfl_xor_sync(0xffffffffu, mx0, 2));
        mx1 = fmaxf(mx1, __shfl_xor_sync(0xffffffffu, mx1, 1));
        mx1 = fmaxf(mx1, __shfl_xor_sync(0xffffffffu, mx1, 2));
        float nm0 = fmaxf(m0, mx0), nm1 = fmaxf(m1, mx1);
        float c0 = __expf(m0 - nm0), c1 = __expf(m1 - nm1);
        float rs0 = 0.f, rs1 = 0.f;
#pragma unroll
        for (int nt = 0; nt < 8; nt++) {
            s[nt].x = __expf(s[nt].x - nm0);
            s[nt].y = __expf(s[nt].y - nm0);
            s[nt].z = __expf(s[nt].z - nm1);
            s[nt].w = __expf(s[nt].w - nm1);
            rs0 += s[nt].x + s[nt].y;
            rs1 += s[nt].z + s[nt].w;
        }
        rs0 += __shfl_xor_sync(0xffffffffu, rs0, 1);
        rs0 += __shfl_xor_sync(0xffffffffu, rs0, 2);
        rs1 += __shfl_xor_sync(0xffffffffu, rs1, 1);
        rs1 += __shfl_xor_sync(0xffffffffu, rs1, 2);
        l0 = l0 * c0 + rs0;
        l1 = l1 * c1 + rs1;
        m0 = nm0; m1 = nm1;

#pragma unroll
        for (int nt = 0; nt < 8; nt++) {
            o[nt].x *= c0; o[nt].y *= c0;
            o[nt].z *= c1; o[nt].w *= c1;
        }

        // P -> smem (rounded to tf32 once, here)
#pragma unroll
        for (int nt = 0; nt < 8; nt++) {
            *(float2*)&PS[r0 * PSW + nt * 8 + 2 * tig] =
                make_float2(tf32f(s[nt].x), tf32f(s[nt].y));
            *(float2*)&PS[(r0 + 8) * PSW + nt * 8 + 2 * tig] =
                make_float2(tf32f(s[nt].z), tf32f(s[nt].w));
        }
        if (tig == 0) {
            size_t mb = (size_t)(bh * NKT + t) * SEQ + qt * QB;
            g_mt[mb + r0] = m0;
            g_mt[mb + r0 + 8] = m1;
        }
        __syncthreads();

        // coalesced bf16 P cache store
        {
            size_t strip = (size_t)(bh * NKT + t) * SEQ + qt * QB;
#pragma unroll
            for (int it = 0; it < 16; it++) {
                int f = tid + it * 256;
                int i = f >> 5, mp = (f & 31) * 2;
                float2 p2 = *(const float2*)&PS[i * PSW + mp];
                *(__nv_bfloat162*)&g_p[(strip + i) * KT + mp] =
                    __floats2bfloat162_rn(p2.x, p2.y);
            }
        }

        // O += P V  (no cvt)
#pragma unroll
        for (int kt = 0; kt < 8; kt++) {
            uint32_t a[4];
            a[0] = __float_as_uint(PS[r0 * PSW + kt * 8 + tig]);
            a[1] = __float_as_uint(PS[(r0 + 8) * PSW + kt * 8 + tig]);
            a[2] = __float_as_uint(PS[r0 * PSW + kt * 8 + tig + 4]);
            a[3] = __float_as_uint(PS[(r0 + 8) * PSW + kt * 8 + tig + 4]);
#pragma unroll
            for (int nt = 0; nt < 8; nt++) {
                uint32_t b0 = __float_as_uint(VS[(kt * 8 + tig) * VSW + nt * 8 + gid]);
                uint32_t b1 = __float_as_uint(VS[(kt * 8 + tig + 4) * VSW + nt * 8 + gid]);
                mma_tf32(o[nt], a, b0, b1);
            }
        }
    }

    // epilogue: ctx as bf16 hi/lo split (for the proj GEMM)
    float i0 = 1.0f / l0, i1 = 1.0f / l1;
    size_t cb = ((size_t)b * SEQ + qt * QB) * DMODEL + h * DK;
#pragma unroll
    for (int nt = 0; nt < 8; nt++) {
        int col = nt * 8 + 2 * tig;
        float v0 = o[nt].x * i0, v1 = o[nt].y * i0;
        float v2 = o[nt].z * i1, v3 = o[nt].w * i1;
        __nv_bfloat16 h0, l0b, h1, l1b, h2, l2b, h3, l3b;
        bsplit(v0, h0, l0b); bsplit(v1, h1, l1b);
        bsplit(v2, h2, l2b); bsplit(v3, h3, l3b);
        __nv_bfloat162 ph, pl;
        ph.x = h0; ph.y = h1; pl.x = l0b; pl.y = l1b;
        *(__nv_bfloat162*)&g_chi[cb + (size_t)r0 * DMODEL + col] = ph;
        *(__nv_bfloat162*)&g_clo[cb + (size_t)r0 * DMODEL + col] = pl;
        ph.x = h2; ph.y = h3; pl.x = l2b; pl.y = l3b;
        *(__nv_bfloat162*)&g_chi[cb + (size_t)(r0 + 8) * DMODEL + col] = ph;
        *(__nv_bfloat162*)&g_clo[cb + (size_t)(r0 + 8) * DMODEL + col] = pl;
    }
    if (tig == 0) {
        size_t rb = (size_t)bh * SEQ + qt * QB;
        g_mf[rb + r0] = m0;  g_il[rb + r0] = i0;
        g_mf[rb + r0 + 8] = m1;  g_il[rb + r0 + 8] = i1;
    }
}

// ---------------- colsum over cached P ----------------
__global__ __launch_bounds__(256) void colsum_kernel() {
    const int kt = blockIdx.x, bh = blockIdx.y, b = bh >> 4;
    const int tid = threadIdx.x, tx = tid & 15, ty = tid >> 4;
    __shared__ float red[16][68];

    float c0 = 0.f, c1 = 0.f, c2 = 0.f, c3 = 0.f;
    const size_t strip = (size_t)(bh * NKT + kt) * SEQ;
    const float* mtp = g_mt + strip;
    const float* mfp = g_mf + (size_t)bh * SEQ;
    const float* ilp = g_il + (size_t)bh * SEQ;

    for (int r = ty; r < SEQ; r += 16) {
        float f = __expf(mtp[r] - mfp[r]) * ilp[r];
        const __nv_bfloat16* pp = g_p + (strip + r) * KT + tx * 4;
        __nv_bfloat162 pa = *(const __nv_bfloat162*)pp;
        __nv_bfloat162 pb = *(const __nv_bfloat162*)(pp + 2);
        float2 fa = __bfloat1622float2(pa);
        float2 fb = __bfloat1622float2(pb);
        c0 += f * fa.x; c1 += f * fa.y; c2 += f * fb.x; c3 += f * fb.y;
    }
    red[ty][tx * 4 + 0] = c0;
    red[ty][tx * 4 + 1] = c1;
    red[ty][tx * 4 + 2] = c2;
    red[ty][tx * 4 + 3] = c3;
    __syncthreads();
    if (tid < 64) {
        float ssum = 0.0f;
#pragma unroll
        for (int y = 0; y < 16; y++) ssum += red[y][tid];
        atomicAdd(&g_colsum[b * SEQ + kt * KT + tid], ssum);
    }
}

// ---------------- launch ----------------
extern "C" void kernel_launch(void* const* d_in, const int* in_sizes, int n_in,
                              void* d_out, int out_size) {
    const float* x     = (const float*)d_in[0];
    const float* w_qkv = (const float*)d_in[1];
    const float* b_qkv = (const float*)d_in[2];
    const float* w_out = (const float*)d_in[3];
    const float* b_out = (const float*)d_in[4];
    float* out = (float*)d_out;

    float* qkv_p;
    cudaGetSymbolAddress((void**)&qkv_p, g_qkv);
    __nv_bfloat16 *xhi, *xlo, *wqh, *wql, *woh, *wol, *chi, *clo;
    cudaGetSymbolAddress((void**)&xhi, g_xhi);
    cudaGetSymbolAddress((void**)&xlo, g_xlo);
    cudaGetSymbolAddress((void**)&wqh, g_wqh);
    cudaGetSymbolAddress((void**)&wql, g_wql);
    cudaGetSymbolAddress((void**)&woh, g_woh);
    cudaGetSymbolAddress((void**)&wol, g_wol);
    cudaGetSymbolAddress((void**)&chi, g_chi);
    cudaGetSymbolAddress((void**)&clo, g_clo);

    cudaFuncSetAttribute(flash_tc,
                         cudaFuncAttributeMaxDynamicSharedMemorySize, FLASH_SMEM_BYTES);
    cudaFuncSetAttribute(gemm_bf16s,
                         cudaFuncAttributeMaxDynamicSharedMemorySize,
                         GEMM_SMEM_BF16 * 2);

    zero_colsum_kernel<<<(BATCH * SEQ + 255) / 256, 256>>>();

    // split inputs into bf16 hi/lo
    {
        int n4 = ROWS * DMODEL / 4;
        split4_kernel<<<(n4 + 255) / 256, 256>>>(
            (const float4*)x, (__nv_bfloat162*)xhi, (__nv_bfloat162*)xlo, n4);
        n4 = DMODEL * QKVC / 4;
        split4_kernel<<<(n4 + 255) / 256, 256>>>(
            (const float4*)w_qkv, (__nv_bfloat162*)wqh, (__nv_bfloat162*)wql, n4);
        n4 = DMODEL * DMODEL / 4;
        split4_kernel<<<(n4 + 255) / 256, 256>>>(
            (const float4*)w_out, (__nv_bfloat162*)woh, (__nv_bfloat162*)wol, n4);
    }

    // QKV projection (bf16 split, tf32-rounded output)
    gemm_bf16s<<<dim3(QKVC / 128, ROWS / 128), 256, GEMM_SMEM_BF16 * 2>>>(
        xhi, xlo, wqh, wql, b_qkv, qkv_p, QKVC, DMODEL, 1);

    // flash attention
    flash_tc<<<dim3(SEQ / QB, BATCH * NHEADS), 256, FLASH_SMEM_BYTES>>>();

    // colsum for attn_mean
    colsum_kernel<<<dim3(NKT, BATCH * NHEADS), 256>>>();

    // output projection (bf16 split, exact output)
    gemm_bf16s<<<dim3(DMODEL / 128, ROWS / 128), 256, GEMM_SMEM_BF16 * 2>>>(
        chi, clo, woh, wol, b_out, out, DMODEL, DMODEL, 0);

    finalize_mean_kernel<<<(BATCH * SEQ + 255) / 256, 256>>>(
        out + (size_t)ROWS * DMODEL);
}